// round 4
// baseline (speedup 1.0000x reference)
#include <cuda_runtime.h>
#include <math.h>

typedef unsigned long long ull;

#define S_LEN   128
#define BATCH   1024
#define D0      300
#define D1      74
#define D2      35
#define HID     40
#define EMB     256
#define MM      3
#define RED_DIM 115            // 2*HID + D2
#define LSTM_IN 121            // RED_DIM + 2*MM
#define KTOT    377            // LSTM_IN + EMB
#define KPAD    384            // 12 chunks * 32
#define NROWS   (S_LEN*BATCH)
#define NBLK    128
#define GRP     8              // blocks per bt-group barrier
#define A_STR   33             // ull stride per A row (32 k + 1 pad)

// -------------------- device scratch --------------------
__device__ float g_reduced[(size_t)NROWS * RED_DIM];   // [S*B][115]
__device__ float g_h[2][BATCH * EMB];                  // ping-pong hidden state
__device__ unsigned g_counts[16];                      // per-bt-group barrier counters

__device__ __forceinline__ float sigm(float x) { return 1.f / (1.f + expf(-x)); }

__device__ __forceinline__ ull pack2(float lo, float hi) {
    ull r;
    asm("mov.b64 %0, {%1, %2};" : "=l"(r) : "f"(lo), "f"(hi));
    return r;
}
__device__ __forceinline__ void unpack2(ull v, float& lo, float& hi) {
    asm("mov.b64 {%0, %1}, %2;" : "=f"(lo), "=f"(hi) : "l"(v));
}
#define FMA2(acc, a, w) asm("fma.rn.f32x2 %0, %1, %2, %0;" : "+l"(acc) : "l"(a), "l"(w))

// -------------------- init --------------------
__global__ void init_kernel() {
    int i = blockIdx.x * blockDim.x + threadIdx.x;
    if (i < 16) g_counts[i] = 0u;
    if (i < BATCH * EMB) {
        g_h[0][i] = 0.f;
        g_h[1][i] = 0.f;
    }
}

// -------------------- phase 1: reduced = [x0@W0.T+b0 | x1@W1.T+b1 | x2] --------------------
__global__ void phase1_kernel(const float* __restrict__ x0, const float* __restrict__ x1,
                              const float* __restrict__ x2,
                              const float* __restrict__ W0, const float* __restrict__ b0p,
                              const float* __restrict__ W1, const float* __restrict__ b1p) {
    extern __shared__ float sm[];
    float* sW0 = sm;                 // 40*300
    float* sW1 = sm + 40 * 300;      // 40*76 (cols 74,75 zero)
    const int tid = threadIdx.x;

    for (int i = tid; i < 40 * 300; i += 320) sW0[i] = W0[i];
    for (int i = tid; i < 40 * 76; i += 320) {
        int r = i / 76, c = i % 76;
        sW1[i] = (c < D1) ? W1[r * D1 + c] : 0.f;
    }
    __syncthreads();

    const int r0 = blockIdx.x * 32;
    const int o  = tid % 40;
    const int rb = (tid / 40) * 4;

    {
        const float bv = b0p[o];
        float acc[4] = {bv, bv, bv, bv};
        const float4* wv = (const float4*)(sW0 + o * D0);
        const float4* xr[4];
#pragma unroll
        for (int j = 0; j < 4; j++)
            xr[j] = (const float4*)(x0 + (size_t)(r0 + rb + j) * D0);
#pragma unroll 5
        for (int k4 = 0; k4 < 75; k4++) {
            float4 w = wv[k4];
#pragma unroll
            for (int j = 0; j < 4; j++) {
                float4 a = __ldg(&xr[j][k4]);
                acc[j] += w.x * a.x + w.y * a.y + w.z * a.z + w.w * a.w;
            }
        }
#pragma unroll
        for (int j = 0; j < 4; j++)
            g_reduced[(size_t)(r0 + rb + j) * RED_DIM + o] = acc[j];
    }
    {
        const float bv = b1p[o];
        float acc[4] = {bv, bv, bv, bv};
        const float2* wv = (const float2*)(sW1 + o * 76);
        const float2* xr[4];
#pragma unroll
        for (int j = 0; j < 4; j++)
            xr[j] = (const float2*)(x1 + (size_t)(r0 + rb + j) * D1);
#pragma unroll 4
        for (int k2 = 0; k2 < 37; k2++) {
            float2 w = wv[k2];
#pragma unroll
            for (int j = 0; j < 4; j++) {
                float2 a = __ldg(&xr[j][k2]);
                acc[j] += w.x * a.x + w.y * a.y;
            }
        }
#pragma unroll
        for (int j = 0; j < 4; j++)
            g_reduced[(size_t)(r0 + rb + j) * RED_DIM + HID + o] = acc[j];
    }
    for (int i = tid; i < 32 * D2; i += 320) {
        int r = i / D2, c = i % D2;
        g_reduced[(size_t)(r0 + r) * RED_DIM + 2 * HID + c] =
            x2[(size_t)(r0 + r) * D2 + c];
    }
}

// -------------------- persistent recurrent kernel --------------------
// grid = 128 blocks, 1/SM, block = 256 threads. Block (bt,et): batch rows
// [bt*64,+64), gate-cols [et*32,+32) of all 4 gates. Weights resident in smem
// as gate-pair-packed ull: (W_i,W_f) and (W_g,W_o). GEMM inner loop uses
// fma.rn.f32x2 (2 fp32 MACs/instr). sA double-buffered with register prefetch.
// Cell state lives in registers. Per-bt-group (8-block) barrier between steps.
__global__ void __launch_bounds__(256, 1) persist_kernel(
    const float* __restrict__ W_ih, const float* __restrict__ W_hh,
    const float* __restrict__ b_ih, const float* __restrict__ b_hh,
    const float* __restrict__ W_dec, const float* __restrict__ b_dec,
    const float* __restrict__ gum, float* __restrict__ out) {

    extern __shared__ __align__(16) ull smd[];
    ull*   sB2   = smd;                        // [KPAD*64]      = 24576 ull (192 KB)
    ull*   sA0   = smd + KPAD * 64;            // [64*A_STR]     = 2112 ull
    ull*   sA1   = sA0 + 64 * A_STR;           // [64*A_STR]
    float* sPrev = (float*)(sA1 + 64 * A_STR); // [64*6]

    const int tid  = threadIdx.x;
    const int lane = tid & 31;
    const int warp = tid >> 5;                 // 0..7
    const int bt   = blockIdx.x & 15;
    const int et   = blockIdx.x >> 4;          // 0..7
    const int bb0  = bt * 64;
    const int e0   = et * 32;
    const int e    = e0 + lane;

    // ---- one-time: weight slab, gate-pair packed ----
    // sB2[k*64 + pair*32 + col] = ( W[2*pair][e0+col][k], W[2*pair+1][e0+col][k] )
    for (int i = tid; i < KPAD * 64; i += 256) {
        int k = i >> 6, idx = i & 63;
        int pair = idx >> 5, col = idx & 31;
        int grow0 = (2 * pair) * EMB + e0 + col;
        int grow1 = grow0 + EMB;
        float w0, w1;
        if (k < LSTM_IN)      { w0 = W_ih[grow0 * LSTM_IN + k];        w1 = W_ih[grow1 * LSTM_IN + k]; }
        else if (k < KTOT)    { w0 = W_hh[grow0 * EMB + k - LSTM_IN];  w1 = W_hh[grow1 * EMB + k - LSTM_IN]; }
        else                  { w0 = 0.f; w1 = 0.f; }
        sB2[i] = pack2(w0, w1);
    }
    ull biaIF = pack2(b_ih[0 * EMB + e] + b_hh[0 * EMB + e],
                      b_ih[1 * EMB + e] + b_hh[1 * EMB + e]);
    ull biaGO = pack2(b_ih[2 * EMB + e] + b_hh[2 * EMB + e],
                      b_ih[3 * EMB + e] + b_hh[3 * EMB + e]);

    // register-resident cell state: c for rows warp*8+j, col e
    float creg[8];
#pragma unroll
    for (int j = 0; j < 8; j++) creg[j] = 0.f;

    // prefetch mapping: this thread owns row pr, k-offsets pk..pk+7 of each chunk
    const int pr = tid >> 2;          // 0..63
    const int pk = (tid & 3) * 8;     // 0,8,16,24
    const int pb = bb0 + pr;

    volatile unsigned* bar = &g_counts[bt];

    for (int t = 0; t <= S_LEN; t++) {
        const float* __restrict__ hprev = g_h[t & 1];
        const float* __restrict__ red_t = g_reduced + (size_t)t * BATCH * RED_DIM;

        float pf[8];
        // ---- prefetch chunk 0 (k 0..31 < RED_DIM: pure red_t, no h/sPrev dep) ----
        if (t < S_LEN) {
#pragma unroll
            for (int q = 0; q < 8; q++)
                pf[q] = __ldg(&red_t[(size_t)pb * RED_DIM + pk + q]);
        }

        // ---------------- prologue: decoder + gumbel for step t-1 ----------------
        if (t == 0) {
            for (int i = tid; i < 64 * 6; i += 256) sPrev[i] = 0.f;
        } else {
            const int tprev = t - 1;
            const bool wr = (et == 0);
            for (int r2 = 0; r2 < 8; r2++) {
                const int b = bb0 + warp * 8 + r2;
                float hv[8];
#pragma unroll
                for (int i = 0; i < 8; i++) hv[i] = __ldcg(&hprev[b * EMB + lane + 32 * i]);
                float lg[6];
#pragma unroll
                for (int mo = 0; mo < 6; mo++) {
                    float p = 0.f;
#pragma unroll
                    for (int i = 0; i < 8; i++)
                        p += hv[i] * __ldg(&W_dec[mo * EMB + lane + 32 * i]);
                    p += __shfl_xor_sync(0xffffffffu, p, 16);
                    p += __shfl_xor_sync(0xffffffffu, p, 8);
                    p += __shfl_xor_sync(0xffffffffu, p, 4);
                    p += __shfl_xor_sync(0xffffffffu, p, 2);
                    p += __shfl_xor_sync(0xffffffffu, p, 1);
                    p += __ldg(&b_dec[mo]);
                    lg[mo] = p;
                    if (lane == mo) sPrev[(warp * 8 + r2) * 6 + mo] = p;
                }
                if (wr && lane < MM) {
                    const int m = lane;
                    size_t gbase = ((size_t)tprev * (MM * BATCH) + m * BATCH + b) * 2;
                    float u0 = gum[gbase], u1 = gum[gbase + 1];
                    float gg0 = -logf(-logf(u0));
                    float gg1 = -logf(-logf(u1));
                    float l0 = lg[2 * m], l1 = lg[2 * m + 1];
                    out[((size_t)tprev * MM + m) * BATCH + b] =
                        (l1 + gg1 > l0 + gg0) ? 1.f : 0.f;
                    size_t lbase = (size_t)S_LEN * MM * BATCH +
                                   (((size_t)tprev * MM + m) * BATCH + b) * 2;
                    out[lbase]     = l0;
                    out[lbase + 1] = l1;
                }
            }
        }
        if (t == S_LEN) break;
        __syncthreads();                       // sPrev ready

        // ---- stage chunk 0, prefetch chunk 1 ----
        {
            ull* dst = sA0 + pr * A_STR + pk;
#pragma unroll
            for (int q = 0; q < 8; q++) dst[q] = pack2(pf[q], pf[q]);
#pragma unroll
            for (int q = 0; q < 8; q++) {
                int kg = 32 + pk + q;          // chunk 1: 32..63 < RED_DIM
                pf[q] = __ldg(&red_t[(size_t)pb * RED_DIM + kg]);
            }
        }
        __syncthreads();                       // sA0 ready

        ull accIF[8], accGO[8];
#pragma unroll
        for (int j = 0; j < 8; j++) { accIF[j] = biaIF; accGO[j] = biaGO; }

        for (int c = 0; c < 12; c++) {
            const ull* bk = sB2 + (size_t)c * 32 * 64;
            const ull* ak = ((c & 1) ? sA1 : sA0) + warp * 8 * A_STR;
#pragma unroll 8
            for (int k = 0; k < 32; k++) {
                ull wIF = bk[k * 64 + lane];
                ull wGO = bk[k * 64 + 32 + lane];
#pragma unroll
                for (int j = 0; j < 8; j++) {
                    ull a = ak[j * A_STR + k];
                    FMA2(accIF[j], a, wIF);
                    FMA2(accGO[j], a, wGO);
                }
            }
            __syncthreads();                   // all done reading buf[(c+1)&1]
            if (c + 1 < 12) {
                ull* dst = ((c & 1) ? sA0 : sA1) + pr * A_STR + pk;
#pragma unroll
                for (int q = 0; q < 8; q++) dst[q] = pack2(pf[q], pf[q]);
                if (c + 2 < 12) {
                    const int kb = (c + 2) * 32 + pk;
#pragma unroll
                    for (int q = 0; q < 8; q++) {
                        int kg = kb + q;
                        float v;
                        if (kg < RED_DIM)        v = __ldg(&red_t[(size_t)pb * RED_DIM + kg]);
                        else if (kg < LSTM_IN)   v = sPrev[pr * 6 + (kg - RED_DIM)];
                        else if (kg < KTOT)      v = __ldcg(&hprev[pb * EMB + (kg - LSTM_IN)]);
                        else                     v = 0.f;
                        pf[q] = v;
                    }
                }
            }
            __syncthreads();                   // next buffer ready
        }

        // ---------------- LSTM cell epilogue ----------------
        const int nb = (t + 1) & 1;
#pragma unroll
        for (int j = 0; j < 8; j++) {
            const int b = bb0 + warp * 8 + j;
            float iv_raw, fv_raw, gv_raw, ov_raw;
            unpack2(accIF[j], iv_raw, fv_raw);
            unpack2(accGO[j], gv_raw, ov_raw);
            float iv = sigm(iv_raw);
            float fv = sigm(fv_raw);
            float gv = tanhf(gv_raw);
            float ov = sigm(ov_raw);
            float cn = fv * creg[j] + iv * gv;
            creg[j] = cn;
            g_h[nb][b * EMB + e] = ov * tanhf(cn);
        }

        // ---------------- per-bt-group barrier (8 blocks) ----------------
        __syncthreads();
        if (tid == 0) {
            __threadfence();
            atomicAdd((unsigned*)bar, 1u);
            const unsigned tgt = (unsigned)(t + 1) * GRP;
            while (*bar < tgt) __nanosleep(32);
        }
        __syncthreads();
    }
}

// -------------------- launch --------------------
extern "C" void kernel_launch(void* const* d_in, const int* in_sizes, int n_in,
                              void* d_out, int out_size) {
    const float* x0    = (const float*)d_in[0];
    const float* x1    = (const float*)d_in[1];
    const float* x2    = (const float*)d_in[2];
    // d_in[3] = x_lens (unused)
    const float* gum   = (const float*)d_in[4];
    const float* W0    = (const float*)d_in[5];
    const float* b0    = (const float*)d_in[6];
    const float* W1    = (const float*)d_in[7];
    const float* b1    = (const float*)d_in[8];
    const float* W_ih  = (const float*)d_in[9];
    const float* W_hh  = (const float*)d_in[10];
    const float* b_ih  = (const float*)d_in[11];
    const float* b_hh  = (const float*)d_in[12];
    const float* W_dec = (const float*)d_in[13];
    const float* b_dec = (const float*)d_in[14];
    float* out = (float*)d_out;

    init_kernel<<<(BATCH * EMB + 255) / 256, 256>>>();

    size_t smem1 = (size_t)(40 * 300 + 40 * 76) * sizeof(float);   // 60160 B
    cudaFuncSetAttribute(phase1_kernel,
                         cudaFuncAttributeMaxDynamicSharedMemorySize, (int)smem1);
    phase1_kernel<<<NROWS / 32, 320, smem1>>>(x0, x1, x2, W0, b0, W1, b1);

    size_t smemP = (size_t)(KPAD * 64 + 2 * 64 * A_STR) * sizeof(ull) +
                   (size_t)(64 * 6) * sizeof(float);               // 231,936 B
    cudaFuncSetAttribute(persist_kernel,
                         cudaFuncAttributeMaxDynamicSharedMemorySize, (int)smemP);
    persist_kernel<<<NBLK, 256, smemP>>>(W_ih, W_hh, b_ih, b_hh,
                                         W_dec, b_dec, gum, out);
}

// round 6
// speedup vs baseline: 1.3012x; 1.3012x over previous
#include <cuda_runtime.h>
#include <math.h>
#include <stdint.h>

typedef unsigned long long ull;

#define S_LEN   128
#define BATCH   1024
#define D0      300
#define D1      74
#define D2      35
#define HID     40
#define EMB     256
#define MM      3
#define RED_DIM 115            // 2*HID + D2
#define LSTM_IN 121            // RED_DIM + 2*MM
#define KTOT    377            // LSTM_IN + EMB
#define KPAD    384            // 12 chunks * 32
#define NCH     12
#define NROWS   (S_LEN*BATCH)
#define NBLK    128

#define W_STR   388            // smem stride (floats) for resident W_hi  (388%32==4 -> conflict-free frags)
#define A_STR   36             // smem stride (floats) for A / W_lo chunks (36%32==4)

// ---- smem layout (float offsets) ----
#define OFF_WHI  0
#define OFF_WLO  (OFF_WHI + 64 * W_STR)          // 24832
#define OFF_AHI  (OFF_WLO + 64 * A_STR)          // 27136
#define OFF_ALO  (OFF_AHI + 128 * A_STR)         // 31744
#define OFF_PREV (OFF_ALO + 128 * A_STR)         // 36352 (128*6)
#define OFF_BIAS (OFF_PREV + 128 * 6)            // 37120 (64)
#define SMEM_F   (OFF_BIAS + 64)                 // 37184 floats = 148736 B
// stage (128 x 65 = 8320 floats) aliases [OFF_AHI, OFF_AHI+9216)

// ---------------- device scratch ----------------
__device__ float g_reduced[(size_t)NROWS * RED_DIM];   // [S*B][115]
__device__ float g_h[2][BATCH * EMB];                  // ping-pong hidden state
__device__ float g_wlo[1024 * KPAD];                   // tf32 low part of W rows
__device__ unsigned g_counts[8];                       // per-bt barrier counters

__device__ __forceinline__ float sigm(float x) { return 1.f / (1.f + expf(-x)); }
__device__ __forceinline__ float to_tf32(float x) {
    float r; asm("cvt.rna.tf32.f32 %0, %1;" : "=f"(r) : "f"(x)); return r;
}

// m16n8k8 tf32 MMA, fp32 accumulate in-place
__device__ __forceinline__ void mma8(float* d,
        uint32_t a0, uint32_t a1, uint32_t a2, uint32_t a3,
        uint32_t b0, uint32_t b1) {
    asm volatile(
        "mma.sync.aligned.m16n8k8.row.col.f32.tf32.tf32.f32 "
        "{%0,%1,%2,%3}, {%4,%5,%6,%7}, {%8,%9}, {%0,%1,%2,%3};"
        : "+f"(d[0]), "+f"(d[1]), "+f"(d[2]), "+f"(d[3])
        : "r"(a0), "r"(a1), "r"(a2), "r"(a3), "r"(b0), "r"(b1));
}

// -------------------- init --------------------
__global__ void init_kernel() {
    int i = blockIdx.x * blockDim.x + threadIdx.x;
    if (i < 8) g_counts[i] = 0u;
    if (i < BATCH * EMB) { g_h[0][i] = 0.f; g_h[1][i] = 0.f; }
}

// -------------------- W low-part split (lo pre-rounded to tf32) --------------------
__global__ void wsplit_kernel(const float* __restrict__ W_ih, const float* __restrict__ W_hh) {
    int idx = blockIdx.x * blockDim.x + threadIdx.x;
    if (idx >= 1024 * KPAD) return;
    int grow = idx / KPAD, k = idx % KPAD;
    float w;
    if (k < LSTM_IN)     w = W_ih[grow * LSTM_IN + k];
    else if (k < KTOT)   w = W_hh[grow * EMB + (k - LSTM_IN)];
    else                 w = 0.f;
    g_wlo[idx] = to_tf32(w - to_tf32(w));
}

// -------------------- phase 1 (proven) --------------------
__global__ void phase1_kernel(const float* __restrict__ x0, const float* __restrict__ x1,
                              const float* __restrict__ x2,
                              const float* __restrict__ W0, const float* __restrict__ b0p,
                              const float* __restrict__ W1, const float* __restrict__ b1p) {
    extern __shared__ float sm[];
    float* sW0 = sm;
    float* sW1 = sm + 40 * 300;
    const int tid = threadIdx.x;

    for (int i = tid; i < 40 * 300; i += 320) sW0[i] = W0[i];
    for (int i = tid; i < 40 * 76; i += 320) {
        int r = i / 76, c = i % 76;
        sW1[i] = (c < D1) ? W1[r * D1 + c] : 0.f;
    }
    __syncthreads();

    const int r0 = blockIdx.x * 32;
    const int o  = tid % 40;
    const int rb = (tid / 40) * 4;
    {
        const float bv = b0p[o];
        float acc[4] = {bv, bv, bv, bv};
        const float4* wv = (const float4*)(sW0 + o * D0);
        const float4* xr[4];
#pragma unroll
        for (int j = 0; j < 4; j++) xr[j] = (const float4*)(x0 + (size_t)(r0 + rb + j) * D0);
#pragma unroll 5
        for (int k4 = 0; k4 < 75; k4++) {
            float4 w = wv[k4];
#pragma unroll
            for (int j = 0; j < 4; j++) {
                float4 a = __ldg(&xr[j][k4]);
                acc[j] += w.x * a.x + w.y * a.y + w.z * a.z + w.w * a.w;
            }
        }
#pragma unroll
        for (int j = 0; j < 4; j++)
            g_reduced[(size_t)(r0 + rb + j) * RED_DIM + o] = acc[j];
    }
    {
        const float bv = b1p[o];
        float acc[4] = {bv, bv, bv, bv};
        const float2* wv = (const float2*)(sW1 + o * 76);
        const float2* xr[4];
#pragma unroll
        for (int j = 0; j < 4; j++) xr[j] = (const float2*)(x1 + (size_t)(r0 + rb + j) * D1);
#pragma unroll 4
        for (int k2 = 0; k2 < 37; k2++) {
            float2 w = wv[k2];
#pragma unroll
            for (int j = 0; j < 4; j++) {
                float2 a = __ldg(&xr[j][k2]);
                acc[j] += w.x * a.x + w.y * a.y;
            }
        }
#pragma unroll
        for (int j = 0; j < 4; j++)
            g_reduced[(size_t)(r0 + rb + j) * RED_DIM + HID + o] = acc[j];
    }
    for (int i = tid; i < 32 * D2; i += 320) {
        int r = i / D2, c = i % D2;
        g_reduced[(size_t)(r0 + r) * RED_DIM + 2 * HID + c] = x2[(size_t)(r0 + r) * D2 + c];
    }
}

// -------------------- persistent mma.sync recurrent kernel --------------------
// grid = 128 (bt 0..7 x et 0..15), block 256. Block: batch rows [bt*128,+128),
// gate-cols [et*16,+16) of all 4 gates (N=64 local cols, col j = gate*16+ei).
// W_hi tf32 resident in smem; W_lo streamed per chunk; A hi/lo per chunk with
// register prefetch overlapping MMA. 4-term tf32 split => fp32-level accuracy.
__global__ void __launch_bounds__(256, 1) persist_kernel(
    const float* __restrict__ W_ih, const float* __restrict__ W_hh,
    const float* __restrict__ b_ih, const float* __restrict__ b_hh,
    const float* __restrict__ W_dec, const float* __restrict__ b_dec,
    const float* __restrict__ gum, float* __restrict__ out) {

    extern __shared__ float smf[];

    const int tid  = threadIdx.x;
    const int lane = tid & 31;
    const int warp = tid >> 5;                 // 0..7
    const int wr   = warp & 3;                 // warp row: 32 batch rows
    const int wc   = warp >> 2;                // warp col: 32 of 64 gate-cols
    const int bt   = blockIdx.x >> 4;          // 0..7
    const int et   = blockIdx.x & 15;          // 0..15
    const int bb0  = bt * 128;
    const int e0   = et * 16;

    const int g    = lane >> 2;                // fragment group 0..7
    const int q    = lane & 3;                 // fragment quad 0..3

    float* sWhi  = smf + OFF_WHI;
    float* sWlo  = smf + OFF_WLO;
    float* sAhi  = smf + OFF_AHI;
    float* sAlo  = smf + OFF_ALO;
    float* sPrev = smf + OFF_PREV;
    float* sBias = smf + OFF_BIAS;
    float* stg   = smf + OFF_AHI;              // stage aliases A buffers

    // ---- one-time: resident W_hi (tf32-rounded), bias ----
    for (int i = tid; i < 64 * KPAD; i += 256) {
        int col = i / KPAD, k = i % KPAD;      // col = gate*16+ei (local)
        int grow = (col >> 4) * EMB + e0 + (col & 15);
        float w;
        if (k < LSTM_IN)     w = W_ih[grow * LSTM_IN + k];
        else if (k < KTOT)   w = W_hh[grow * EMB + (k - LSTM_IN)];
        else                 w = 0.f;
        sWhi[col * W_STR + k] = to_tf32(w);
    }
    if (tid < 64) {
        int gg = tid >> 4, ei = tid & 15;
        sBias[tid] = b_ih[gg * EMB + e0 + ei] + b_hh[gg * EMB + e0 + ei];
    }
    __syncthreads();

    float creg[8];
#pragma unroll
    for (int j = 0; j < 8; j++) creg[j] = 0.f;

    // prefetch mapping
    const int pr  = tid >> 1;                  // A row 0..127
    const int pko = (tid & 1) * 16;            // A k-offset 0 or 16
    const int pb  = bb0 + pr;
    const int pwc = tid >> 2;                  // W col 0..63
    const int pwk = (tid & 3) * 8;             // W k-offset 0,8,16,24
    const int pwrow = (pwc >> 4) * EMB + e0 + (pwc & 15);

    volatile unsigned* bar = &g_counts[bt];

    for (int t = 0; t <= S_LEN; t++) {
        const float* __restrict__ hprev = g_h[t & 1];
        const float* __restrict__ red_t = g_reduced + (size_t)t * BATCH * RED_DIM;

        float pf[16], pw[8];
        if (t < S_LEN) {
            // chunk 0 (k<32 < RED_DIM): pure red_t + wlo
#pragma unroll
            for (int x = 0; x < 16; x++)
                pf[x] = __ldg(&red_t[(size_t)pb * RED_DIM + pko + x]);
            {
                const float4* src = (const float4*)(g_wlo + (size_t)pwrow * KPAD + pwk);
                float4 v0 = src[0], v1 = src[1];
                pw[0] = v0.x; pw[1] = v0.y; pw[2] = v0.z; pw[3] = v0.w;
                pw[4] = v1.x; pw[5] = v1.y; pw[6] = v1.z; pw[7] = v1.w;
            }
        }

        // ---------------- decoder prologue for step t-1 ----------------
        if (t == 0) {
            for (int i = tid; i < 128 * 6; i += 256) sPrev[i] = 0.f;
        } else {
            const int tprev = t - 1;
            const bool wrt = (et == 0);
            for (int r2 = 0; r2 < 16; r2++) {
                const int rloc = warp * 16 + r2;
                const int b = bb0 + rloc;
                float hv[8];
#pragma unroll
                for (int i = 0; i < 8; i++) hv[i] = __ldcg(&hprev[b * EMB + lane + 32 * i]);
                float lg[6];
#pragma unroll
                for (int mo = 0; mo < 6; mo++) {
                    float p = 0.f;
#pragma unroll
                    for (int i = 0; i < 8; i++)
                        p += hv[i] * __ldg(&W_dec[mo * EMB + lane + 32 * i]);
                    p += __shfl_xor_sync(0xffffffffu, p, 16);
                    p += __shfl_xor_sync(0xffffffffu, p, 8);
                    p += __shfl_xor_sync(0xffffffffu, p, 4);
                    p += __shfl_xor_sync(0xffffffffu, p, 2);
                    p += __shfl_xor_sync(0xffffffffu, p, 1);
                    p += __ldg(&b_dec[mo]);
                    lg[mo] = p;
                    if (lane == mo) sPrev[rloc * 6 + mo] = p;
                }
                if (wrt && lane < MM) {
                    const int m = lane;
                    size_t gbase = ((size_t)tprev * (MM * BATCH) + m * BATCH + b) * 2;
                    float u0 = gum[gbase], u1 = gum[gbase + 1];
                    float gg0 = -logf(-logf(u0));
                    float gg1 = -logf(-logf(u1));
                    float l0 = lg[2 * m], l1 = lg[2 * m + 1];
                    out[((size_t)tprev * MM + m) * BATCH + b] =
                        (l1 + gg1 > l0 + gg0) ? 1.f : 0.f;
                    size_t lbase = (size_t)S_LEN * MM * BATCH +
                                   (((size_t)tprev * MM + m) * BATCH + b) * 2;
                    out[lbase]     = l0;
                    out[lbase + 1] = l1;
                }
            }
        }
        if (t == S_LEN) break;

        float acc[2][4][4];
#pragma unroll
        for (int mt = 0; mt < 2; mt++)
#pragma unroll
            for (int nt = 0; nt < 4; nt++)
#pragma unroll
                for (int x = 0; x < 4; x++) acc[mt][nt][x] = 0.f;

        // ---------------- chunk loop ----------------
        for (int c = 0; c < NCH; c++) {
            // ---- store prefetched chunk to smem (hi/lo split) ----
#pragma unroll
            for (int x = 0; x < 16; x++) {
                float v  = pf[x];
                float hi = to_tf32(v);
                sAhi[pr * A_STR + pko + x] = hi;
                sAlo[pr * A_STR + pko + x] = to_tf32(v - hi);
            }
#pragma unroll
            for (int x = 0; x < 8; x++)
                sWlo[pwc * A_STR + pwk + x] = pw[x];
            __syncthreads();

            // ---- prefetch chunk c+1 (overlaps MMA below) ----
            if (c + 1 < NCH) {
                const int kb = (c + 1) * 32 + pko;
#pragma unroll
                for (int x = 0; x < 16; x++) {
                    int kg = kb + x;
                    float v;
                    if (kg < RED_DIM)       v = __ldg(&red_t[(size_t)pb * RED_DIM + kg]);
                    else if (kg < LSTM_IN)  v = sPrev[pr * 6 + (kg - RED_DIM)];
                    else if (kg < KTOT)     v = __ldcg(&hprev[pb * EMB + (kg - LSTM_IN)]);
                    else                    v = 0.f;
                    pf[x] = v;
                }
                const float4* src = (const float4*)(g_wlo + (size_t)pwrow * KPAD +
                                                    (c + 1) * 32 + pwk);
                float4 v0 = src[0], v1 = src[1];
                pw[0] = v0.x; pw[1] = v0.y; pw[2] = v0.z; pw[3] = v0.w;
                pw[4] = v1.x; pw[5] = v1.y; pw[6] = v1.z; pw[7] = v1.w;
            }

            // ---- MMA: 4 k8 steps, 4-term split ----
            const uint32_t* uAh = (const uint32_t*)sAhi;
            const uint32_t* uAl = (const uint32_t*)sAlo;
            const uint32_t* uWh = (const uint32_t*)sWhi;
            const uint32_t* uWl = (const uint32_t*)sWlo;
#pragma unroll
            for (int kk = 0; kk < 4; kk++) {
                const int k0 = kk * 8;
                uint32_t ah[2][4], al[2][4];
#pragma unroll
                for (int mt = 0; mt < 2; mt++) {
                    const int r0m = wr * 32 + mt * 16 + g;
                    ah[mt][0] = uAh[r0m * A_STR + k0 + q];
                    ah[mt][1] = uAh[(r0m + 8) * A_STR + k0 + q];
                    ah[mt][2] = uAh[r0m * A_STR + k0 + q + 4];
                    ah[mt][3] = uAh[(r0m + 8) * A_STR + k0 + q + 4];
                    al[mt][0] = uAl[r0m * A_STR + k0 + q];
                    al[mt][1] = uAl[(r0m + 8) * A_STR + k0 + q];
                    al[mt][2] = uAl[r0m * A_STR + k0 + q + 4];
                    al[mt][3] = uAl[(r0m + 8) * A_STR + k0 + q + 4];
                }
#pragma unroll
                for (int nt = 0; nt < 4; nt++) {
                    const int col = wc * 32 + nt * 8 + g;
                    uint32_t bh0 = uWh[col * W_STR + c * 32 + k0 + q];
                    uint32_t bh1 = uWh[col * W_STR + c * 32 + k0 + q + 4];
                    uint32_t bl0 = uWl[col * A_STR + k0 + q];
                    uint32_t bl1 = uWl[col * A_STR + k0 + q + 4];
#pragma unroll
                    for (int mt = 0; mt < 2; mt++) {
                        mma8(acc[mt][nt], ah[mt][0], ah[mt][1], ah[mt][2], ah[mt][3], bh0, bh1);
                        mma8(acc[mt][nt], ah[mt][0], ah[mt][1], ah[mt][2], ah[mt][3], bl0, bl1);
                        mma8(acc[mt][nt], al[mt][0], al[mt][1], al[mt][2], al[mt][3], bh0, bh1);
                        mma8(acc[mt][nt], al[mt][0], al[mt][1], al[mt][2], al[mt][3], bl0, bl1);
                    }
                }
            }
            __syncthreads();
        }

        // ---------------- epilogue: accums -> stage -> LSTM cell ----------------
#pragma unroll
        for (int mt = 0; mt < 2; mt++)
#pragma unroll
            for (int nt = 0; nt < 4; nt++) {
                const int r0m  = wr * 32 + mt * 16 + g;
                const int col0 = wc * 32 + nt * 8 + 2 * q;
                stg[r0m * 65 + col0]           = acc[mt][nt][0];
                stg[r0m * 65 + col0 + 1]       = acc[mt][nt][1];
                stg[(r0m + 8) * 65 + col0]     = acc[mt][nt][2];
                stg[(r0m + 8) * 65 + col0 + 1] = acc[mt][nt][3];
            }
        __syncthreads();
        {
            const int r = tid >> 1, ei0 = (tid & 1) * 8;
            const int b = bb0 + r;
            const int nb = (t + 1) & 1;
            float hrow[8];
#pragma unroll
            for (int x = 0; x < 8; x++) {
                int ei = ei0 + x;
                float iv = stg[r * 65 + 0  + ei] + sBias[0 * 16 + ei];
                float fv = stg[r * 65 + 16 + ei] + sBias[1 * 16 + ei];
                float gv = stg[r * 65 + 32 + ei] + sBias[2 * 16 + ei];
                float ov = stg[r * 65 + 48 + ei] + sBias[3 * 16 + ei];
                float i_ = sigm(iv), f_ = sigm(fv), g_ = tanhf(gv), o_ = sigm(ov);
                float cn = f_ * creg[x] + i_ * g_;
                creg[x] = cn;
                hrow[x] = o_ * tanhf(cn);
            }
            float* hdst = &g_h[nb][b * EMB + e0 + ei0];
            *(float4*)(hdst)     = make_float4(hrow[0], hrow[1], hrow[2], hrow[3]);
            *(float4*)(hdst + 4) = make_float4(hrow[4], hrow[5], hrow[6], hrow[7]);
        }

        // ---------------- bt-group barrier (16 blocks) ----------------
        __syncthreads();
        if (tid == 0) {
            __threadfence();
            atomicAdd((unsigned*)bar, 1u);
            const unsigned tgt = (unsigned)(t + 1) * 16u;
            while (*bar < tgt) __nanosleep(32);
        }
        __syncthreads();
    }
}

// -------------------- launch --------------------
extern "C" void kernel_launch(void* const* d_in, const int* in_sizes, int n_in,
                              void* d_out, int out_size) {
    const float* x0    = (const float*)d_in[0];
    const float* x1    = (const float*)d_in[1];
    const float* x2    = (const float*)d_in[2];
    // d_in[3] = x_lens (unused)
    const float* gum   = (const float*)d_in[4];
    const float* W0    = (const float*)d_in[5];
    const float* b0    = (const float*)d_in[6];
    const float* W1    = (const float*)d_in[7];
    const float* b1    = (const float*)d_in[8];
    const float* W_ih  = (const float*)d_in[9];
    const float* W_hh  = (const float*)d_in[10];
    const float* b_ih  = (const float*)d_in[11];
    const float* b_hh  = (const float*)d_in[12];
    const float* W_dec = (const float*)d_in[13];
    const float* b_dec = (const float*)d_in[14];
    float* out = (float*)d_out;

    init_kernel<<<(BATCH * EMB + 255) / 256, 256>>>();
    wsplit_kernel<<<(1024 * KPAD + 255) / 256, 256>>>(W_ih, W_hh);

    size_t smem1 = (size_t)(40 * 300 + 40 * 76) * sizeof(float);
    cudaFuncSetAttribute(phase1_kernel,
                         cudaFuncAttributeMaxDynamicSharedMemorySize, (int)smem1);
    phase1_kernel<<<NROWS / 32, 320, smem1>>>(x0, x1, x2, W0, b0, W1, b1);

    size_t smemP = (size_t)SMEM_F * sizeof(float);   // 148736 B
    cudaFuncSetAttribute(persist_kernel,
                         cudaFuncAttributeMaxDynamicSharedMemorySize, (int)smemP);
    persist_kernel<<<NBLK, 256, smemP>>>(W_ih, W_hh, b_ih, b_hh,
                                         W_dec, b_dec, gum, out);
}

// round 7
// speedup vs baseline: 1.5244x; 1.1715x over previous
#include <cuda_runtime.h>
#include <math.h>
#include <stdint.h>

typedef unsigned long long ull;

#define S_LEN   128
#define BATCH   1024
#define D0      300
#define D1      74
#define D2      35
#define HID     40
#define EMB     256
#define MM      3
#define RED_DIM 115            // 2*HID + D2
#define LSTM_IN 121            // RED_DIM + 2*MM
#define KTOT    377            // LSTM_IN + EMB
#define KPAD    384            // 12 chunks * 32
#define NCH     12
#define NROWS   (S_LEN*BATCH)
#define NBLK    128
#define THR     512

#define W_STR   388            // resident W_hi stride (388%32==4 -> conflict-free frags)
#define A_STR   36             // A / W_lo chunk stride (36%32==4)

// ---- smem layout (float offsets) ----
#define OFF_WHI  0                               // 64*388      = 24832
#define OFF_WLO  (OFF_WHI + 64 * W_STR)          // 2*64*36     = 4608
#define OFF_AHI  (OFF_WLO + 2 * 64 * A_STR)      // 2*128*36    = 9216
#define OFF_ALO  (OFF_AHI + 2 * 128 * A_STR)     // 2*128*36    = 9216
#define OFF_PREV (OFF_ALO + 2 * 128 * A_STR)     // 128*6       = 768
#define OFF_BIAS (OFF_PREV + 128 * 6)            // 64
#define SMEM_F   (OFF_BIAS + 64)                 // 48704 floats = 194816 B
// epilogue stage (128*65=8320 floats) aliases the A buffers at OFF_AHI

// ---------------- device scratch ----------------
__device__ float g_reduced[(size_t)NROWS * RED_DIM];
__device__ float g_h[2][BATCH * EMB];
__device__ float g_wlo[1024 * KPAD];
__device__ unsigned g_counts[8];

__device__ __forceinline__ float sigm(float x) { return 1.f / (1.f + expf(-x)); }
__device__ __forceinline__ float to_tf32(float x) {
    float r; asm("cvt.rna.tf32.f32 %0, %1;" : "=f"(r) : "f"(x)); return r;
}
__device__ __forceinline__ void mma8(float* d,
        uint32_t a0, uint32_t a1, uint32_t a2, uint32_t a3,
        uint32_t b0, uint32_t b1) {
    asm volatile(
        "mma.sync.aligned.m16n8k8.row.col.f32.tf32.tf32.f32 "
        "{%0,%1,%2,%3}, {%4,%5,%6,%7}, {%8,%9}, {%0,%1,%2,%3};"
        : "+f"(d[0]), "+f"(d[1]), "+f"(d[2]), "+f"(d[3])
        : "r"(a0), "r"(a1), "r"(a2), "r"(a3), "r"(b0), "r"(b1));
}

// -------------------- init --------------------
__global__ void init_kernel() {
    int i = blockIdx.x * blockDim.x + threadIdx.x;
    if (i < 8) g_counts[i] = 0u;
    if (i < BATCH * EMB) { g_h[0][i] = 0.f; g_h[1][i] = 0.f; }
}

// -------------------- W low-part split --------------------
__global__ void wsplit_kernel(const float* __restrict__ W_ih, const float* __restrict__ W_hh) {
    int idx = blockIdx.x * blockDim.x + threadIdx.x;
    if (idx >= 1024 * KPAD) return;
    int grow = idx / KPAD, k = idx % KPAD;
    float w;
    if (k < LSTM_IN)     w = W_ih[grow * LSTM_IN + k];
    else if (k < KTOT)   w = W_hh[grow * EMB + (k - LSTM_IN)];
    else                 w = 0.f;
    g_wlo[idx] = to_tf32(w - to_tf32(w));
}

// -------------------- phase 1 (proven) --------------------
__global__ void phase1_kernel(const float* __restrict__ x0, const float* __restrict__ x1,
                              const float* __restrict__ x2,
                              const float* __restrict__ W0, const float* __restrict__ b0p,
                              const float* __restrict__ W1, const float* __restrict__ b1p) {
    extern __shared__ float sm[];
    float* sW0 = sm;
    float* sW1 = sm + 40 * 300;
    const int tid = threadIdx.x;

    for (int i = tid; i < 40 * 300; i += 320) sW0[i] = W0[i];
    for (int i = tid; i < 40 * 76; i += 320) {
        int r = i / 76, c = i % 76;
        sW1[i] = (c < D1) ? W1[r * D1 + c] : 0.f;
    }
    __syncthreads();

    const int r0 = blockIdx.x * 32;
    const int o  = tid % 40;
    const int rb = (tid / 40) * 4;
    {
        const float bv = b0p[o];
        float acc[4] = {bv, bv, bv, bv};
        const float4* wv = (const float4*)(sW0 + o * D0);
        const float4* xr[4];
#pragma unroll
        for (int j = 0; j < 4; j++) xr[j] = (const float4*)(x0 + (size_t)(r0 + rb + j) * D0);
#pragma unroll 5
        for (int k4 = 0; k4 < 75; k4++) {
            float4 w = wv[k4];
#pragma unroll
            for (int j = 0; j < 4; j++) {
                float4 a = __ldg(&xr[j][k4]);
                acc[j] += w.x * a.x + w.y * a.y + w.z * a.z + w.w * a.w;
            }
        }
#pragma unroll
        for (int j = 0; j < 4; j++)
            g_reduced[(size_t)(r0 + rb + j) * RED_DIM + o] = acc[j];
    }
    {
        const float bv = b1p[o];
        float acc[4] = {bv, bv, bv, bv};
        const float2* wv = (const float2*)(sW1 + o * 76);
        const float2* xr[4];
#pragma unroll
        for (int j = 0; j < 4; j++) xr[j] = (const float2*)(x1 + (size_t)(r0 + rb + j) * D1);
#pragma unroll 4
        for (int k2 = 0; k2 < 37; k2++) {
            float2 w = wv[k2];
#pragma unroll
            for (int j = 0; j < 4; j++) {
                float2 a = __ldg(&xr[j][k2]);
                acc[j] += w.x * a.x + w.y * a.y;
            }
        }
#pragma unroll
        for (int j = 0; j < 4; j++)
            g_reduced[(size_t)(r0 + rb + j) * RED_DIM + HID + o] = acc[j];
    }
    for (int i = tid; i < 32 * D2; i += 320) {
        int r = i / D2, c = i % D2;
        g_reduced[(size_t)(r0 + r) * RED_DIM + 2 * HID + c] = x2[(size_t)(r0 + r) * D2 + c];
    }
}

// -------------------- persistent mma.sync recurrent kernel (16 warps) --------------------
// grid = 128 (bt 0..7 x et 0..15), block 512 = 16 warps (4x4 warp grid).
// Warp (wr,wc): rows wr*32 + {0..31}, cols wc*16 + {0..15} of the 64 local gate-cols.
// Double-buffered A/W_lo (1 sync per chunk); split accumulators accP/accQ.
__global__ void __launch_bounds__(THR, 1) persist_kernel(
    const float* __restrict__ W_ih, const float* __restrict__ W_hh,
    const float* __restrict__ b_ih, const float* __restrict__ b_hh,
    const float* __restrict__ W_dec, const float* __restrict__ b_dec,
    const float* __restrict__ gum, float* __restrict__ out) {

    extern __shared__ float smf[];

    const int tid  = threadIdx.x;
    const int lane = tid & 31;
    const int warp = tid >> 5;                 // 0..15
    const int wr   = warp & 3;                 // warp row (32 rows)
    const int wc   = warp >> 2;                // warp col (16 cols)
    const int bt   = blockIdx.x >> 4;
    const int et   = blockIdx.x & 15;
    const int bb0  = bt * 128;
    const int e0   = et * 16;

    const int g    = lane >> 2;
    const int q    = lane & 3;

    float* sWhi  = smf + OFF_WHI;
    float* sWlo  = smf + OFF_WLO;              // 2 bufs of 64*A_STR
    float* sAhi  = smf + OFF_AHI;              // 2 bufs of 128*A_STR
    float* sAlo  = smf + OFF_ALO;
    float* sPrev = smf + OFF_PREV;
    float* sBias = smf + OFF_BIAS;
    float* stg   = smf + OFF_AHI;              // epilogue stage aliases A buffers

    // ---- one-time: resident W_hi (tf32-rounded), bias ----
    for (int i = tid; i < 64 * KPAD; i += THR) {
        int col = i / KPAD, k = i % KPAD;
        int grow = (col >> 4) * EMB + e0 + (col & 15);
        float w;
        if (k < LSTM_IN)     w = W_ih[grow * LSTM_IN + k];
        else if (k < KTOT)   w = W_hh[grow * EMB + (k - LSTM_IN)];
        else                 w = 0.f;
        sWhi[col * W_STR + k] = to_tf32(w);
    }
    if (tid < 64) {
        int gg = tid >> 4, ei = tid & 15;
        sBias[tid] = b_ih[gg * EMB + e0 + ei] + b_hh[gg * EMB + e0 + ei];
    }
    __syncthreads();

    float creg[4];
#pragma unroll
    for (int j = 0; j < 4; j++) creg[j] = 0.f;

    // fill mappings
    const int pr  = tid >> 2;                  // A row 0..127
    const int pko = (tid & 3) * 8;             // A k-offset 0,8,16,24
    const int pb  = bb0 + pr;
    const int pwc = tid >> 3;                  // W col 0..63
    const int pwk = (tid & 7) * 4;             // W k-offset 0..28
    const int pwrow = (pwc >> 4) * EMB + e0 + (pwc & 15);

    volatile unsigned* bar = &g_counts[bt];

    for (int t = 0; t <= S_LEN; t++) {
        const float* __restrict__ hprev = g_h[t & 1];
        const float* __restrict__ red_t = g_reduced + (size_t)t * BATCH * RED_DIM;

        float pf[8], pw[4];
        if (t < S_LEN) {
            // chunk 0: k<32 < RED_DIM, no h/sPrev dependency
#pragma unroll
            for (int x = 0; x < 8; x++)
                pf[x] = __ldg(&red_t[(size_t)pb * RED_DIM + pko + x]);
            {
                float4 v = *(const float4*)(g_wlo + (size_t)pwrow * KPAD + pwk);
                pw[0] = v.x; pw[1] = v.y; pw[2] = v.z; pw[3] = v.w;
            }
        }

        // ---------------- decoder prologue for step t-1 ----------------
        if (t == 0) {
            for (int i = tid; i < 128 * 6; i += THR) sPrev[i] = 0.f;
        } else {
            const int tprev = t - 1;
            const bool wrt = (et == 0);
            for (int r2 = 0; r2 < 8; r2++) {
                const int rloc = warp * 8 + r2;
                const int b = bb0 + rloc;
                float hv[8];
#pragma unroll
                for (int i = 0; i < 8; i++) hv[i] = __ldcg(&hprev[b * EMB + lane + 32 * i]);
                float lg[6];
#pragma unroll
                for (int mo = 0; mo < 6; mo++) {
                    float p = 0.f;
#pragma unroll
                    for (int i = 0; i < 8; i++)
                        p += hv[i] * __ldg(&W_dec[mo * EMB + lane + 32 * i]);
                    p += __shfl_xor_sync(0xffffffffu, p, 16);
                    p += __shfl_xor_sync(0xffffffffu, p, 8);
                    p += __shfl_xor_sync(0xffffffffu, p, 4);
                    p += __shfl_xor_sync(0xffffffffu, p, 2);
                    p += __shfl_xor_sync(0xffffffffu, p, 1);
                    p += __ldg(&b_dec[mo]);
                    lg[mo] = p;
                    if (lane == mo) sPrev[rloc * 6 + mo] = p;
                }
                if (wrt && lane < MM) {
                    const int m = lane;
                    size_t gbase = ((size_t)tprev * (MM * BATCH) + m * BATCH + b) * 2;
                    float u0 = gum[gbase], u1 = gum[gbase + 1];
                    float gg0 = -logf(-logf(u0));
                    float gg1 = -logf(-logf(u1));
                    float l0 = lg[2 * m], l1 = lg[2 * m + 1];
                    out[((size_t)tprev * MM + m) * BATCH + b] =
                        (l1 + gg1 > l0 + gg0) ? 1.f : 0.f;
                    size_t lbase = (size_t)S_LEN * MM * BATCH +
                                   (((size_t)tprev * MM + m) * BATCH + b) * 2;
                    out[lbase]     = l0;
                    out[lbase + 1] = l1;
                }
            }
        }
        if (t == S_LEN) break;

        // ---- stage chunk 0 into buf0; prefetch chunk 1 ----
        {
#pragma unroll
            for (int x = 0; x < 8; x++) {
                float v  = pf[x];
                float hi = to_tf32(v);
                sAhi[pr * A_STR + pko + x] = hi;
                sAlo[pr * A_STR + pko + x] = to_tf32(v - hi);
            }
#pragma unroll
            for (int x = 0; x < 4; x++) sWlo[pwc * A_STR + pwk + x] = pw[x];
            const int kb = 32 + pko;           // chunk 1: still < RED_DIM
#pragma unroll
            for (int x = 0; x < 8; x++)
                pf[x] = __ldg(&red_t[(size_t)pb * RED_DIM + kb + x]);
            float4 v = *(const float4*)(g_wlo + (size_t)pwrow * KPAD + 32 + pwk);
            pw[0] = v.x; pw[1] = v.y; pw[2] = v.z; pw[3] = v.w;
        }
        __syncthreads();

        float accP[2][2][4], accQ[2][2][4];
#pragma unroll
        for (int mt = 0; mt < 2; mt++)
#pragma unroll
            for (int nt = 0; nt < 2; nt++)
#pragma unroll
                for (int x = 0; x < 4; x++) { accP[mt][nt][x] = 0.f; accQ[mt][nt][x] = 0.f; }

        // ---------------- chunk loop (1 sync/chunk) ----------------
        for (int c = 0; c < NCH; c++) {
            const int buf  = c & 1;
            const int nbuf = buf ^ 1;

            // stage prefetched chunk c+1 into nbuf; prefetch c+2
            if (c + 1 < NCH) {
                float* dAh = sAhi + nbuf * 128 * A_STR;
                float* dAl = sAlo + nbuf * 128 * A_STR;
                float* dWl = sWlo + nbuf * 64 * A_STR;
#pragma unroll
                for (int x = 0; x < 8; x++) {
                    float v  = pf[x];
                    float hi = to_tf32(v);
                    dAh[pr * A_STR + pko + x] = hi;
                    dAl[pr * A_STR + pko + x] = to_tf32(v - hi);
                }
#pragma unroll
                for (int x = 0; x < 4; x++) dWl[pwc * A_STR + pwk + x] = pw[x];
                if (c + 2 < NCH) {
                    const int kb = (c + 2) * 32 + pko;
#pragma unroll
                    for (int x = 0; x < 8; x++) {
                        int kg = kb + x;
                        float v;
                        if (kg < RED_DIM)       v = __ldg(&red_t[(size_t)pb * RED_DIM + kg]);
                        else if (kg < LSTM_IN)  v = sPrev[pr * 6 + (kg - RED_DIM)];
                        else if (kg < KTOT)     v = __ldcg(&hprev[pb * EMB + (kg - LSTM_IN)]);
                        else                    v = 0.f;
                        pf[x] = v;
                    }
                    float4 v = *(const float4*)(g_wlo + (size_t)pwrow * KPAD +
                                                (c + 2) * 32 + pwk);
                    pw[0] = v.x; pw[1] = v.y; pw[2] = v.z; pw[3] = v.w;
                }
            }

            // MMA on buf
            const uint32_t* uAh = (const uint32_t*)(sAhi + buf * 128 * A_STR);
            const uint32_t* uAl = (const uint32_t*)(sAlo + buf * 128 * A_STR);
            const uint32_t* uWh = (const uint32_t*)sWhi;
            const uint32_t* uWl = (const uint32_t*)(sWlo + buf * 64 * A_STR);
#pragma unroll
            for (int kk = 0; kk < 4; kk++) {
                const int k0 = kk * 8;
                uint32_t ah[2][4], al[2][4];
#pragma unroll
                for (int mt = 0; mt < 2; mt++) {
                    const int r0m = wr * 32 + mt * 16 + g;
                    ah[mt][0] = uAh[r0m * A_STR + k0 + q];
                    ah[mt][1] = uAh[(r0m + 8) * A_STR + k0 + q];
                    ah[mt][2] = uAh[r0m * A_STR + k0 + q + 4];
                    ah[mt][3] = uAh[(r0m + 8) * A_STR + k0 + q + 4];
                    al[mt][0] = uAl[r0m * A_STR + k0 + q];
                    al[mt][1] = uAl[(r0m + 8) * A_STR + k0 + q];
                    al[mt][2] = uAl[r0m * A_STR + k0 + q + 4];
                    al[mt][3] = uAl[(r0m + 8) * A_STR + k0 + q + 4];
                }
#pragma unroll
                for (int nt = 0; nt < 2; nt++) {
                    const int col = wc * 16 + nt * 8 + g;
                    uint32_t bh0 = uWh[col * W_STR + c * 32 + k0 + q];
                    uint32_t bh1 = uWh[col * W_STR + c * 32 + k0 + q + 4];
                    uint32_t bl0 = uWl[col * A_STR + k0 + q];
                    uint32_t bl1 = uWl[col * A_STR + k0 + q + 4];
#pragma unroll
                    for (int mt = 0; mt < 2; mt++) {
                        mma8(accP[mt][nt], ah[mt][0], ah[mt][1], ah[mt][2], ah[mt][3], bh0, bh1);
                        mma8(accQ[mt][nt], ah[mt][0], ah[mt][1], ah[mt][2], ah[mt][3], bl0, bl1);
                        mma8(accQ[mt][nt], al[mt][0], al[mt][1], al[mt][2], al[mt][3], bh0, bh1);
                        mma8(accP[mt][nt], al[mt][0], al[mt][1], al[mt][2], al[mt][3], bl0, bl1);
                    }
                }
            }
            __syncthreads();
        }

        // ---------------- epilogue: accs -> stage -> LSTM cell ----------------
#pragma unroll
        for (int mt = 0; mt < 2; mt++)
#pragma unroll
            for (int nt = 0; nt < 2; nt++) {
                const int r0m  = wr * 32 + mt * 16 + g;
                const int col0 = wc * 16 + nt * 8 + 2 * q;
                stg[r0m * 65 + col0]           = accP[mt][nt][0] + accQ[mt][nt][0];
                stg[r0m * 65 + col0 + 1]       = accP[mt][nt][1] + accQ[mt][nt][1];
                stg[(r0m + 8) * 65 + col0]     = accP[mt][nt][2] + accQ[mt][nt][2];
                stg[(r0m + 8) * 65 + col0 + 1] = accP[mt][nt][3] + accQ[mt][nt][3];
            }
        __syncthreads();
        {
            const int r = tid >> 2, ei0 = (tid & 3) * 4;
            const int b = bb0 + r;
            const int nb = (t + 1) & 1;
            float hrow[4];
#pragma unroll
            for (int x = 0; x < 4; x++) {
                int ei = ei0 + x;
                float iv = stg[r * 65 + 0  + ei] + sBias[0 * 16 + ei];
                float fv = stg[r * 65 + 16 + ei] + sBias[1 * 16 + ei];
                float gv = stg[r * 65 + 32 + ei] + sBias[2 * 16 + ei];
                float ov = stg[r * 65 + 48 + ei] + sBias[3 * 16 + ei];
                float i_ = sigm(iv), f_ = sigm(fv), g_ = tanhf(gv), o_ = sigm(ov);
                float cn = f_ * creg[x] + i_ * g_;
                creg[x] = cn;
                hrow[x] = o_ * tanhf(cn);
            }
            *(float4*)(&g_h[nb][b * EMB + e0 + ei0]) =
                make_float4(hrow[0], hrow[1], hrow[2], hrow[3]);
        }

        // ---------------- bt-group barrier (16 blocks) ----------------
        __syncthreads();
        if (tid == 0) {
            __threadfence();
            atomicAdd((unsigned*)bar, 1u);
            const unsigned tgt = (unsigned)(t + 1) * 16u;
            while (*bar < tgt) __nanosleep(32);
        }
        __syncthreads();
    }
}

// -------------------- launch --------------------
extern "C" void kernel_launch(void* const* d_in, const int* in_sizes, int n_in,
                              void* d_out, int out_size) {
    const float* x0    = (const float*)d_in[0];
    const float* x1    = (const float*)d_in[1];
    const float* x2    = (const float*)d_in[2];
    // d_in[3] = x_lens (unused)
    const float* gum   = (const float*)d_in[4];
    const float* W0    = (const float*)d_in[5];
    const float* b0    = (const float*)d_in[6];
    const float* W1    = (const float*)d_in[7];
    const float* b1    = (const float*)d_in[8];
    const float* W_ih  = (const float*)d_in[9];
    const float* W_hh  = (const float*)d_in[10];
    const float* b_ih  = (const float*)d_in[11];
    const float* b_hh  = (const float*)d_in[12];
    const float* W_dec = (const float*)d_in[13];
    const float* b_dec = (const float*)d_in[14];
    float* out = (float*)d_out;

    init_kernel<<<(BATCH * EMB + 255) / 256, 256>>>();
    wsplit_kernel<<<(1024 * KPAD + 255) / 256, 256>>>(W_ih, W_hh);

    size_t smem1 = (size_t)(40 * 300 + 40 * 76) * sizeof(float);
    cudaFuncSetAttribute(phase1_kernel,
                         cudaFuncAttributeMaxDynamicSharedMemorySize, (int)smem1);
    phase1_kernel<<<NROWS / 32, 320, smem1>>>(x0, x1, x2, W0, b0, W1, b1);

    size_t smemP = (size_t)SMEM_F * sizeof(float);   // 194816 B
    cudaFuncSetAttribute(persist_kernel,
                         cudaFuncAttributeMaxDynamicSharedMemorySize, (int)smemP);
    persist_kernel<<<NBLK, THR, smemP>>>(W_ih, W_hh, b_ih, b_hh,
                                         W_dec, b_dec, gum, out);
}